// round 15
// baseline (speedup 1.0000x reference)
#include <cuda_runtime.h>
#include <math.h>

#define NROWS 1024
#define C 64
#define MARGIN_F 15.0f
#define EPSJ 1e-8f
#define HLN2 0.34657359027997264f   /* 0.5*ln2 */

/* gram kernel tiling */
#define GTI 32
#define GTJ 64
/* js kernel tiling: 32i x 16j -> 2048 blocks, full residency */
#define JTI 32
#define JTJ 16
#define NBLKJ 2048                   /* (1024/JTI)*(1024/JTJ), single launch */

typedef unsigned long long ull;

// ---------------- scratch (static device globals; no allocation) ----------------
__device__ float g_K[2][NROWS];      // 0.5*Sa + 0.5*ln2*sumA  per row
__device__ float g_nn[2][NROWS];     // ||x||^2 per row
__device__ float g_pos[2 * NROWS];   // per-row positive-branch contribution
__device__ float g_oodv[2 * NROWS];  // per-row ood contribution (var*coffi)
__device__ float g_rowsum[NROWS];    // negative-branch per-row pair sums
__device__ int   g_rowcnt[NROWS];    // negative-branch per-row counts
__device__ int   g_done;             // js-kernel completion counter
__device__ float g_w[NROWS][NROWS];  // per-pair weight hinge*(1-dl)  (4 MB)

__device__ __forceinline__ ull fma2(ull a, ull b, ull c) {
    ull d;
    asm("fma.rn.f32x2 %0, %1, %2, %3;" : "=l"(d) : "l"(a), "l"(b), "l"(c));
    return d;
}

union F4U {                          // used only in gram kernel (proven)
    float4 f;
    ull u[2];
    float s[4];
    unsigned q[4];
};

__device__ __forceinline__ float wsum(float v) {
    #pragma unroll
    for (int off = 16; off; off >>= 1) v += __shfl_xor_sync(0xffffffffu, v, off);
    return v;
}
__device__ __forceinline__ float wmin(float v) {
    #pragma unroll
    for (int off = 16; off; off >>= 1)
        v = fminf(v, __shfl_xor_sync(0xffffffffu, v, off));
    return v;
}

// ---------------- kernel 1: warp-per-row precompute + positive + ood ------------
__global__ void row_kernel(const float* __restrict__ x1, const float* __restrict__ x2,
                           const float* __restrict__ xp1, const float* __restrict__ xp2,
                           const float* __restrict__ l1,  const float* __restrict__ l2) {
    int gtid = blockIdx.x * blockDim.x + threadIdx.x;
    int w    = gtid >> 5;            // warp id: 0..2047
    int lane = gtid & 31;
    if (gtid == 0) g_done = 0;
    if (gtid < NROWS) { g_rowsum[gtid] = 0.0f; g_rowcnt[gtid] = 0; }

    int br = w >> 10;
    int i  = w & (NROWS - 1);
    const float* xr = (br ? x2  : x1)  + i * C;
    const float* pr = (br ? xp2 : xp1) + i * C;
    const float* lr = (br ? l2  : l1)  + i * C;

    float xv0 = xr[lane], xv1 = xr[lane + 32];
    float A0  = pr[lane] + EPSJ, A1 = pr[lane + 32] + EPSJ;
    float lv0 = lr[lane], lv1 = lr[lane + 32];

    float nn = wsum(fmaf(xv0, xv0, xv1 * xv1));

    float la0 = __logf(A0),                 la1 = __logf(A1);
    float L00 = __logf(0.5f * (A0 + EPSJ)), L01 = __logf(0.5f * (A1 + EPSJ));
    float L10 = __logf(0.5f * (A0 + 1.0f)), L11 = __logf(0.5f * (A1 + 1.0f));
    float P  = fmaf(A0, la0 - L00, A1 * (la1 - L01));
    float T  = L00 + L01;
    float Sa = fmaf(A0, la0, A1 * la1);
    float sA = A0 + A1;

    float pd0 = sqrtf(fmaxf(nn - 2.0f * xv0 + 1.0f, 1e-12f));
    float pd1 = sqrtf(fmaxf(nn - 2.0f * xv1 + 1.0f, 1e-12f));
    float h0  = -0.5f * A0 * (L00 - L10) - 0.5f * EPSJ * L00 + 0.5f * L10;
    float h1  = -0.5f * A1 * (L01 - L11) - 0.5f * EPSJ * L01 + 0.5f * L11;
    float w0  = pd0 * lv0, w1 = pd1 * lv1;
    float S1  = w0 + w1;
    float S2  = fmaf(w0, h0, w1 * h1);
    float r0  = fmaxf(MARGIN_F - pd0, 0.0f) * (1.0f / MARGIN_F);
    float r1  = fmaxf(MARGIN_F - pd1, 0.0f) * (1.0f / MARGIN_F);
    float var = fmaf(r0, r0, r1 * r1);
    float mn  = fminf(1.0f - r0, 1.0f - r1);

    P = wsum(P); T = wsum(T); Sa = wsum(Sa); sA = wsum(sA);
    S1 = wsum(S1); S2 = wsum(S2); var = wsum(var); mn = wmin(mn);

    if (lane == 0) {
        const float LOGEPS = -18.420680743952367f;   // ln(1e-8)
        float G = 1.0f - 0.5f * P - 0.5f * EPSJ * (float)(C - 1) * LOGEPS
                       + 0.5f * EPSJ * T;
        g_pos [w]   = G * S1 + S2;
        g_oodv[w]   = var * mn;
        g_K [br][i] = 0.5f * Sa + HLN2 * sA;
        g_nn[br][i] = nn;
    }
}

// ---------------- kernel 2: gram + weights (unchanged, proven) ------------------
__global__ void __launch_bounds__(128, 4)
gram_kernel(const float* __restrict__ x1, const float* __restrict__ x2,
            const float* __restrict__ l1,  const float* __restrict__ l2) {
    extern __shared__ float sm[];
    float2* sPi = (float2*)sm;            // [C][GTI] (l1,x1)  16 KB
    float2* sPj = sPi + C * GTI;          // [C][GTJ] (l2,x2)  32 KB

    const int tx = threadIdx.x, ty = threadIdx.y;
    const int tid = ty * 16 + tx;
    const int i0 = blockIdx.y * GTI, j0 = blockIdx.x * GTJ;

    {
        int r = tid & 31, c0 = tid >> 5;          // c0: 0..3
        #pragma unroll
        for (int p = 0; p < 4; p++) {
            int cb = c0 + 4 * p;
            float4 lv = *(const float4*)&l1[(i0 + r) * C + cb * 4];
            float4 xv = *(const float4*)&x1[(i0 + r) * C + cb * 4];
            sPi[(cb * 4 + 0) * GTI + r] = make_float2(lv.x, xv.x);
            sPi[(cb * 4 + 1) * GTI + r] = make_float2(lv.y, xv.y);
            sPi[(cb * 4 + 2) * GTI + r] = make_float2(lv.z, xv.z);
            sPi[(cb * 4 + 3) * GTI + r] = make_float2(lv.w, xv.w);
        }
    }
    {
        int r = tid & 63, c0 = tid >> 6;          // c0: 0..1
        #pragma unroll
        for (int p = 0; p < 8; p++) {
            int cb = c0 + 2 * p;
            float4 lv = *(const float4*)&l2[(j0 + r) * C + cb * 4];
            float4 xv = *(const float4*)&x2[(j0 + r) * C + cb * 4];
            sPj[(cb * 4 + 0) * GTJ + r] = make_float2(lv.x, xv.x);
            sPj[(cb * 4 + 1) * GTJ + r] = make_float2(lv.y, xv.y);
            sPj[(cb * 4 + 2) * GTJ + r] = make_float2(lv.z, xv.z);
            sPj[(cb * 4 + 3) * GTJ + r] = make_float2(lv.w, xv.w);
        }
    }
    __syncthreads();

    ull dlx[4][4];
    #pragma unroll
    for (int a = 0; a < 4; a++)
        #pragma unroll
        for (int b = 0; b < 4; b++) dlx[a][b] = 0ull;

    const float4* pi4 = (const float4*)sPi + ty * 2;
    const float4* pj4 = (const float4*)sPj + tx * 2;

    #pragma unroll 4
    for (int c = 0; c < C; c++) {
        F4U pia, pib, pja, pjb;
        pia.f = pi4[c * (GTI / 2)];
        pib.f = pi4[c * (GTI / 2) + 1];
        pja.f = pj4[c * (GTJ / 2)];
        pjb.f = pj4[c * (GTJ / 2) + 1];
        ull pi[4] = {pia.u[0], pia.u[1], pib.u[0], pib.u[1]};
        ull pj[4] = {pja.u[0], pja.u[1], pjb.u[0], pjb.u[1]};
        #pragma unroll
        for (int ki = 0; ki < 4; ki++)
            #pragma unroll
            for (int kj = 0; kj < 4; kj++)
                dlx[ki][kj] = fma2(pi[ki], pj[kj], dlx[ki][kj]);
    }

    F4U nb, na;
    nb.f = *(const float4*)&g_nn[1][j0 + tx * 4];
    na.f = *(const float4*)&g_nn[0][i0 + ty * 4];

    #pragma unroll
    for (int ki = 0; ki < 4; ki++) {
        int i = i0 + ty * 4 + ki;
        F4U wv;
        int rcnt = 0;
        #pragma unroll
        for (int kj = 0; kj < 4; kj++) {
            float2 v = *(float2*)&dlx[ki][kj];           // (dl, dx)
            float d2 = fmaxf(na.s[ki] + nb.s[kj] - 2.0f * v.y, 1e-12f);
            float ed = sqrtf(d2) + 1e-10f;
            float hinge = fmaxf(MARGIN_F - ed, 0.0f);
            float w = hinge * (1.0f - v.x);
            wv.s[kj] = w;
            rcnt += (w > 0.0f) ? 1 : 0;
        }
        *(float4*)&g_w[i][j0 + tx * 4] = wv.f;
        #pragma unroll
        for (int off = 8; off; off >>= 1)
            rcnt += __shfl_down_sync(0xffffffffu, rcnt, off, 16);
        if (tx == 0) atomicAdd(&g_rowcnt[i], rcnt);
    }
}

// Poly log-sum term: acc += s*log2(s) via deg-4 even/odd poly about f=1.5.
// Coefficients validated in round 13 (total rel_err 1.19e-5 at 5/8 usage).
// fma-pipe ~16 cyc, alu ~6 cyc; no MUFU -> overlaps the MUFU path.
__device__ __forceinline__ float jpoly(float s, float acc) {
    int ix = __float_as_int(s);
    float E = __int_as_float((ix >> 23) + 0x4B000000) - 8388735.0f;  // exp-127
    float f = __int_as_float((ix & 0x007FFFFF) | 0x3F800000);        // [1,2)
    float u  = f - 1.5f;
    float u2 = u * u;
    float odd  = fmaf(u2,  0.1543624f,  0.9610546f);   // c3*u^2 + c1
    float even = fmaf(u2, -0.0791602f, -0.3198568f);   // c4*u^2 + c2
    float p = fmaf(u, odd, fmaf(u2, even, 0.5849522f));
    return fmaf(s, p + E, acc);
}

// ---------------- kernel 3: js log-sums, balanced 3-MUFU + 1-poly hybrid --------
// Round-14 result: the pure-MUFU loop is throughput-limited (latency fully
// hidden at 13.8 warps/SMSP). Per c-iter (4 logs) route 1 through the FMA-pipe
// poly and 3 through MUFU: fma ~30 cyc vs mufu ~24-36 -> pipes balanced,
// ~0.7x the pure-MUFU pipe cost. Same 32i x 16j / 2048-block tiling;
// launch_bounds(128,12) (<=42 regs for the poly temps), ~12 blocks/SM.
__global__ void __launch_bounds__(128, 12)
js_kernel(const float* __restrict__ xp1, const float* __restrict__ xp2,
          float* __restrict__ out, int out_size) {
    __shared__ float sA[C * JTI];            // a = xp1+eps   8 KB
    __shared__ float sB[C * JTJ];            // b = xp2+eps   4 KB
    __shared__ int s_last;

    const int tx = threadIdx.x, ty = threadIdx.y;   // tx 0..7, ty 0..15
    const int tid = ty * 8 + tx;
    const int i0 = blockIdx.y * JTI, j0 = blockIdx.x * JTJ;

    {
        int r = tid & 31, c0 = tid >> 5;             // c0: 0..3
        #pragma unroll
        for (int p = 0; p < 4; p++) {
            int cb = c0 + 4 * p;                     // 0..15
            float4 u = *(const float4*)&xp1[(i0 + r) * C + cb * 4];
            sA[(cb * 4 + 0) * JTI + r] = u.x + EPSJ;
            sA[(cb * 4 + 1) * JTI + r] = u.y + EPSJ;
            sA[(cb * 4 + 2) * JTI + r] = u.z + EPSJ;
            sA[(cb * 4 + 3) * JTI + r] = u.w + EPSJ;
        }
    }
    {
        int r = tid & 15, c0 = tid >> 4;             // c0: 0..7
        #pragma unroll
        for (int p = 0; p < 2; p++) {
            int cb = c0 + 8 * p;                     // 0..15
            float4 v = *(const float4*)&xp2[(j0 + r) * C + cb * 4];
            sB[(cb * 4 + 0) * JTJ + r] = v.x + EPSJ;
            sB[(cb * 4 + 1) * JTJ + r] = v.y + EPSJ;
            sB[(cb * 4 + 2) * JTJ + r] = v.z + EPSJ;
            sB[(cb * 4 + 3) * JTJ + r] = v.w + EPSJ;
        }
    }
    __syncthreads();

    float j00 = 0.0f, j01 = 0.0f, j10 = 0.0f, j11 = 0.0f;

    const float2* a2 = (const float2*)sA + ty;       // stride JTI/2=16 per c
    const float2* b2 = (const float2*)sB + tx;       // stride JTJ/2=8  per c

    #pragma unroll 8
    for (int c = 0; c < C; c++) {
        float2 av = a2[c * (JTI / 2)];
        float2 bv = b2[c * (JTJ / 2)];
        // poly path (FMA/ALU pipes): 1 log
        j00 = jpoly(av.x + bv.x, j00);
        // MUFU path: 3 logs
        float s01 = av.x + bv.y;
        float s10 = av.y + bv.x;
        float s11 = av.y + bv.y;
        j01 = fmaf(s01, __log2f(s01), j01);
        j10 = fmaf(s10, __log2f(s10), j10);
        j11 = fmaf(s11, __log2f(s11), j11);
    }

    // W/K loads after the loop (L2-resident; once per block)
    {
        int i = i0 + ty * 2;
        float2 w0 = *(const float2*)&g_w[i + 0][j0 + tx * 2];
        float2 w1 = *(const float2*)&g_w[i + 1][j0 + tx * 2];
        float2 Ka = *(const float2*)&g_K[0][i];
        float2 Kb = *(const float2*)&g_K[1][j0 + tx * 2];

        float rsum0 = w0.x * (Ka.x + Kb.x - HLN2 * j00)
                    + w0.y * (Ka.x + Kb.y - HLN2 * j01);
        float rsum1 = w1.x * (Ka.y + Kb.x - HLN2 * j10)
                    + w1.y * (Ka.y + Kb.y - HLN2 * j11);
        #pragma unroll
        for (int off = 4; off; off >>= 1) {
            rsum0 += __shfl_down_sync(0xffffffffu, rsum0, off, 8);
            rsum1 += __shfl_down_sync(0xffffffffu, rsum1, off, 8);
        }
        if (tx == 0) {
            atomicAdd(&g_rowsum[i + 0], rsum0);
            atomicAdd(&g_rowsum[i + 1], rsum1);
        }
    }

    // ---- folded finalize: last block to finish reduces everything ----
    __threadfence();
    __syncthreads();
    if (tid == 0) s_last = atomicAdd(&g_done, 1);
    __syncthreads();
    if (s_last != NBLKJ - 1) return;

    float nega = 0.0f, posi = 0.0f, ood = 0.0f;
    for (int r = tid; r < NROWS; r += 128) {
        float rs = __ldcg(&g_rowsum[r]);
        int   rc = __ldcg(&g_rowcnt[r]);
        nega += rs / (float)(rc > 0 ? rc : 1);
    }
    for (int r = tid; r < 2 * NROWS; r += 128) {
        posi += g_pos[r];
        ood  += g_oodv[r];
    }
    float* red = sA;                 // reuse smem
    red[tid]       = nega;
    red[128 + tid] = posi;
    red[256 + tid] = ood;
    __syncthreads();
    for (int off = 64; off; off >>= 1) {
        if (tid < off) {
            red[tid]       += red[tid + off];
            red[128 + tid] += red[128 + tid + off];
            red[256 + tid] += red[256 + tid + off];
        }
        __syncthreads();
    }
    for (int r = 3 + tid; r < out_size; r += 128) out[r] = 0.0f;  // defensive
    if (tid == 0) {
        float ng = red[0];
        float ps = 0.5f * red[128];
        float od = 0.5f * red[256];
        if (out_size > 0) out[0] = ps + ng + 0.5f * od;   // LAM = 0.5
        if (out_size > 1) out[1] = ps;
        if (out_size > 2) out[2] = ng;
    }
}

// ---------------- launch ---------------------------------------------------------
extern "C" void kernel_launch(void* const* d_in, const int* in_sizes, int n_in,
                              void* d_out, int out_size) {
    const float* x1  = (const float*)d_in[0];
    const float* x2  = (const float*)d_in[1];
    const float* xp1 = (const float*)d_in[2];
    const float* xp2 = (const float*)d_in[3];
    const float* l1  = (const float*)d_in[4];
    const float* l2  = (const float*)d_in[5];
    float* out = (float*)d_out;

    row_kernel<<<256, 256>>>(x1, x2, xp1, xp2, l1, l2);

    const int gsmem = C * (GTI + GTJ) * (int)sizeof(float2);   // 49,152 B
    cudaFuncSetAttribute(gram_kernel, cudaFuncAttributeMaxDynamicSharedMemorySize,
                         gsmem);
    gram_kernel<<<dim3(NROWS / GTJ, NROWS / GTI), dim3(16, 8), gsmem>>>(x1, x2, l1, l2);

    // single full-grid js launch: 2048 blocks
    js_kernel<<<dim3(NROWS / JTJ, NROWS / JTI), dim3(8, 16)>>>(xp1, xp2, out, out_size);
}

// round 16
// speedup vs baseline: 1.0354x; 1.0354x over previous
#include <cuda_runtime.h>
#include <math.h>

#define NROWS 1024
#define C 64
#define MARGIN_F 15.0f
#define EPSJ 1e-8f
#define HLN2 0.34657359027997264f   /* 0.5*ln2 */
#define TI 32                        /* i-tile (rows of x1) */
#define TJ 64                        /* j-tile (rows of x2) */
#define NBLK 512                     /* (1024/TI)*(1024/TJ) */
#define NTHR 128                     /* threads per block (16x8) */

typedef unsigned long long ull;

// ---------------- scratch (static device globals; no allocation) ----------------
__device__ float g_K[2][NROWS];      // 0.5*Sa + 0.5*ln2*sumA  per row
__device__ float g_nn[2][NROWS];     // ||x||^2 per row
__device__ float g_pos[2 * NROWS];   // per-row positive-branch contribution
__device__ float g_oodv[2 * NROWS];  // per-row ood contribution (var*coffi)
__device__ float g_rowsum[NROWS];    // negative-branch per-row pair sums
__device__ int   g_rowcnt[NROWS];    // negative-branch per-row counts
__device__ int   g_done;             // pair-kernel completion counter

__device__ __forceinline__ ull fma2(ull a, ull b, ull c) {
    ull d;
    asm("fma.rn.f32x2 %0, %1, %2, %3;" : "=l"(d) : "l"(a), "l"(b), "l"(c));
    return d;
}

union F4U {
    float4 f;
    ull u[2];
    float s[4];
};

__device__ __forceinline__ float wsum(float v) {
    #pragma unroll
    for (int off = 16; off; off >>= 1) v += __shfl_xor_sync(0xffffffffu, v, off);
    return v;
}
__device__ __forceinline__ float wmin(float v) {
    #pragma unroll
    for (int off = 16; off; off >>= 1)
        v = fminf(v, __shfl_xor_sync(0xffffffffu, v, off));
    return v;
}

// Poly log-sum term: acc += s*log2(s) via deg-4 even/odd poly about f=1.5.
// Coefficients validated (round 13): total rel_err 1.2e-5 at 5/8 usage; here
// 4/16 usage -> ~5e-6. fma-pipe ~8 ops, alu ~3; no MUFU -> overlaps MUFU path.
__device__ __forceinline__ float jpoly(float s, float acc) {
    int ix = __float_as_int(s);
    float E = __int_as_float((ix >> 23) + 0x4B000000) - 8388735.0f;  // exp-127
    float f = __int_as_float((ix & 0x007FFFFF) | 0x3F800000);        // [1,2)
    float u  = f - 1.5f;
    float u2 = u * u;
    float odd  = fmaf(u2,  0.1543624f,  0.9610546f);   // c3*u^2 + c1
    float even = fmaf(u2, -0.0791602f, -0.3198568f);   // c4*u^2 + c2
    float p = fmaf(u, odd, fmaf(u2, even, 0.5849522f));
    return fmaf(s, p + E, acc);
}

// ---------------- kernel 1: warp-per-row precompute + positive + ood ------------
__global__ void row_kernel(const float* __restrict__ x1, const float* __restrict__ x2,
                           const float* __restrict__ xp1, const float* __restrict__ xp2,
                           const float* __restrict__ l1,  const float* __restrict__ l2) {
    int gtid = blockIdx.x * blockDim.x + threadIdx.x;
    int w    = gtid >> 5;            // warp id: 0..2047
    int lane = gtid & 31;
    if (gtid == 0) g_done = 0;
    if (gtid < NROWS) { g_rowsum[gtid] = 0.0f; g_rowcnt[gtid] = 0; }

    int br = w >> 10;
    int i  = w & (NROWS - 1);
    const float* xr = (br ? x2  : x1)  + i * C;
    const float* pr = (br ? xp2 : xp1) + i * C;
    const float* lr = (br ? l2  : l1)  + i * C;

    float xv0 = xr[lane], xv1 = xr[lane + 32];
    float A0  = pr[lane] + EPSJ, A1 = pr[lane + 32] + EPSJ;
    float lv0 = lr[lane], lv1 = lr[lane + 32];

    float nn = wsum(fmaf(xv0, xv0, xv1 * xv1));

    float la0 = __logf(A0),                 la1 = __logf(A1);
    float L00 = __logf(0.5f * (A0 + EPSJ)), L01 = __logf(0.5f * (A1 + EPSJ));
    float L10 = __logf(0.5f * (A0 + 1.0f)), L11 = __logf(0.5f * (A1 + 1.0f));
    float P  = fmaf(A0, la0 - L00, A1 * (la1 - L01));
    float T  = L00 + L01;
    float Sa = fmaf(A0, la0, A1 * la1);
    float sA = A0 + A1;

    float pd0 = sqrtf(fmaxf(nn - 2.0f * xv0 + 1.0f, 1e-12f));
    float pd1 = sqrtf(fmaxf(nn - 2.0f * xv1 + 1.0f, 1e-12f));
    float h0  = -0.5f * A0 * (L00 - L10) - 0.5f * EPSJ * L00 + 0.5f * L10;
    float h1  = -0.5f * A1 * (L01 - L11) - 0.5f * EPSJ * L01 + 0.5f * L11;
    float w0  = pd0 * lv0, w1 = pd1 * lv1;
    float S1  = w0 + w1;
    float S2  = fmaf(w0, h0, w1 * h1);
    float r0  = fmaxf(MARGIN_F - pd0, 0.0f) * (1.0f / MARGIN_F);
    float r1  = fmaxf(MARGIN_F - pd1, 0.0f) * (1.0f / MARGIN_F);
    float var = fmaf(r0, r0, r1 * r1);
    float mn  = fminf(1.0f - r0, 1.0f - r1);

    P = wsum(P); T = wsum(T); Sa = wsum(Sa); sA = wsum(sA);
    S1 = wsum(S1); S2 = wsum(S2); var = wsum(var); mn = wmin(mn);

    if (lane == 0) {
        const float LOGEPS = -18.420680743952367f;   // ln(1e-8)
        float G = 1.0f - 0.5f * P - 0.5f * EPSJ * (float)(C - 1) * LOGEPS
                       + 0.5f * EPSJ * T;
        g_pos [w]   = G * S1 + S2;
        g_oodv[w]   = var * mn;
        g_K [br][i] = 0.5f * Sa + HLN2 * sA;
        g_nn[br][i] = nn;
    }
}

// ---------------- kernel 2: pairwise negative branch, fused phase-split ---------
// (round-7 architecture — all-time best at 55.3 — with hybrid phase B)
// 32i x 64j tile, 128 threads (16tx x 8ty), micro-tile 4i x 4j CONTIGUOUS:
//   i = i0 + ty*4 + ki,  j = j0 + tx*4 + kj.
// Phase A (grams, 48KB): 4x LDS.128 + 16 packed f32x2 FMA per c-iter -> 16 pairs.
//   w = hinge*(1-dl) in regs; per-row counts (w>0 <=> pairs>0, js>0 strictly).
// Phase B (js, 24KB reused): 2x LDS.128 + 16 logs per c-iter, routed
//   12 -> MUFU.LG2, 4 (diagonal kj==ki) -> FMA-pipe poly. At 4 warps/SMSP:
//   MUFU 384 cyc vs fma ~352 per c-iter -> balanced, ~0.75x pure-MUFU phase B.
__global__ void __launch_bounds__(NTHR, 4)
pair_kernel(const float* __restrict__ x1, const float* __restrict__ x2,
            const float* __restrict__ xp1, const float* __restrict__ xp2,
            const float* __restrict__ l1,  const float* __restrict__ l2,
            float* __restrict__ out, int out_size) {
    extern __shared__ float sm[];
    const int tx = threadIdx.x, ty = threadIdx.y;
    const int tid = ty * 16 + tx;
    const int i0 = blockIdx.y * TI, j0 = blockIdx.x * TJ;

    float wreg[4][4];

    // ================= Phase A: grams =================
    {
        float2* sPi = (float2*)sm;            // [C][TI] (l1,x1)  16 KB
        float2* sPj = sPi + C * TI;           // [C][TJ] (l2,x2)  32 KB

        {
            int r = tid & 31, c0 = tid >> 5;          // c0: 0..3
            #pragma unroll
            for (int p = 0; p < 4; p++) {
                int cb = c0 + 4 * p;                  // 0..15
                float4 lv = *(const float4*)&l1[(i0 + r) * C + cb * 4];
                float4 xv = *(const float4*)&x1[(i0 + r) * C + cb * 4];
                sPi[(cb * 4 + 0) * TI + r] = make_float2(lv.x, xv.x);
                sPi[(cb * 4 + 1) * TI + r] = make_float2(lv.y, xv.y);
                sPi[(cb * 4 + 2) * TI + r] = make_float2(lv.z, xv.z);
                sPi[(cb * 4 + 3) * TI + r] = make_float2(lv.w, xv.w);
            }
        }
        {
            int r = tid & 63, c0 = tid >> 6;          // c0: 0..1
            #pragma unroll
            for (int p = 0; p < 8; p++) {
                int cb = c0 + 2 * p;                  // 0..15
                float4 lv = *(const float4*)&l2[(j0 + r) * C + cb * 4];
                float4 xv = *(const float4*)&x2[(j0 + r) * C + cb * 4];
                sPj[(cb * 4 + 0) * TJ + r] = make_float2(lv.x, xv.x);
                sPj[(cb * 4 + 1) * TJ + r] = make_float2(lv.y, xv.y);
                sPj[(cb * 4 + 2) * TJ + r] = make_float2(lv.z, xv.z);
                sPj[(cb * 4 + 3) * TJ + r] = make_float2(lv.w, xv.w);
            }
        }
        __syncthreads();

        ull dlx[4][4];
        #pragma unroll
        for (int a = 0; a < 4; a++)
            #pragma unroll
            for (int b = 0; b < 4; b++) dlx[a][b] = 0ull;

        const float4* pi4 = (const float4*)sPi + ty * 2;
        const float4* pj4 = (const float4*)sPj + tx * 2;

        #pragma unroll 4
        for (int c = 0; c < C; c++) {
            F4U pia, pib, pja, pjb;
            pia.f = pi4[c * (TI / 2)];
            pib.f = pi4[c * (TI / 2) + 1];
            pja.f = pj4[c * (TJ / 2)];
            pjb.f = pj4[c * (TJ / 2) + 1];
            ull pi[4] = {pia.u[0], pia.u[1], pib.u[0], pib.u[1]};
            ull pj[4] = {pja.u[0], pja.u[1], pjb.u[0], pjb.u[1]};
            #pragma unroll
            for (int ki = 0; ki < 4; ki++)
                #pragma unroll
                for (int kj = 0; kj < 4; kj++)
                    dlx[ki][kj] = fma2(pi[ki], pj[kj], dlx[ki][kj]);
        }

        F4U nb, na;
        nb.f = *(const float4*)&g_nn[1][j0 + tx * 4];
        na.f = *(const float4*)&g_nn[0][i0 + ty * 4];

        #pragma unroll
        for (int ki = 0; ki < 4; ki++) {
            int rcnt = 0;
            #pragma unroll
            for (int kj = 0; kj < 4; kj++) {
                float2 v = *(float2*)&dlx[ki][kj];           // (dl, dx)
                float d2 = fmaxf(na.s[ki] + nb.s[kj] - 2.0f * v.y, 1e-12f);
                float ed = sqrtf(d2) + 1e-10f;
                float hinge = fmaxf(MARGIN_F - ed, 0.0f);
                float wv = hinge * (1.0f - v.x);             // >0 <=> pair counted
                wreg[ki][kj] = wv;
                rcnt += (wv > 0.0f) ? 1 : 0;
            }
            #pragma unroll
            for (int off = 8; off; off >>= 1)
                rcnt += __shfl_down_sync(0xffffffffu, rcnt, off, 16);
            if (tx == 0) atomicAdd(&g_rowcnt[i0 + ty * 4 + ki], rcnt);
        }
        __syncthreads();   // all reads of sPi/sPj done before overwrite
    }

    // ================= Phase B: js log-sums (12 MUFU + 4 poly) =================
    {
        float* sA = sm;                       // [C][TI] xp1+eps   8 KB
        float* sB = sm + C * TI;              // [C][TJ] xp2+eps  16 KB

        {
            int r = tid & 31, c0 = tid >> 5;
            #pragma unroll
            for (int p = 0; p < 4; p++) {
                int cb = c0 + 4 * p;
                float4 v = *(const float4*)&xp1[(i0 + r) * C + cb * 4];
                sA[(cb * 4 + 0) * TI + r] = v.x + EPSJ;
                sA[(cb * 4 + 1) * TI + r] = v.y + EPSJ;
                sA[(cb * 4 + 2) * TI + r] = v.z + EPSJ;
                sA[(cb * 4 + 3) * TI + r] = v.w + EPSJ;
            }
        }
        {
            int r = tid & 63, c0 = tid >> 6;
            #pragma unroll
            for (int p = 0; p < 8; p++) {
                int cb = c0 + 2 * p;
                float4 v = *(const float4*)&xp2[(j0 + r) * C + cb * 4];
                sB[(cb * 4 + 0) * TJ + r] = v.x + EPSJ;
                sB[(cb * 4 + 1) * TJ + r] = v.y + EPSJ;
                sB[(cb * 4 + 2) * TJ + r] = v.z + EPSJ;
                sB[(cb * 4 + 3) * TJ + r] = v.w + EPSJ;
            }
        }
        __syncthreads();

        float jsum[4][4];
        #pragma unroll
        for (int a = 0; a < 4; a++)
            #pragma unroll
            for (int b = 0; b < 4; b++) jsum[a][b] = 0.0f;

        const float4* a4 = (const float4*)sA + ty;      // stride TI/4=8 per c
        const float4* b4 = (const float4*)sB + tx;      // stride TJ/4=16 per c

        #pragma unroll 4
        for (int c = 0; c < C; c++) {
            F4U av, bv;
            av.f = a4[c * (TI / 4)];
            bv.f = b4[c * (TJ / 4)];
            #pragma unroll
            for (int ki = 0; ki < 4; ki++)
                #pragma unroll
                for (int kj = 0; kj < 4; kj++) {
                    float s = av.s[ki] + bv.s[kj];
                    if (kj == ki) {
                        jsum[ki][kj] = jpoly(s, jsum[ki][kj]);        // FMA pipe
                    } else {
                        jsum[ki][kj] = fmaf(s, __log2f(s), jsum[ki][kj]);  // MUFU
                    }
                }
        }

        F4U Kb, Ka;
        Kb.f = *(const float4*)&g_K[1][j0 + tx * 4];
        Ka.f = *(const float4*)&g_K[0][i0 + ty * 4];

        #pragma unroll
        for (int ki = 0; ki < 4; ki++) {
            int i = i0 + ty * 4 + ki;
            float rsum = 0.0f;
            #pragma unroll
            for (int kj = 0; kj < 4; kj++) {
                float js = Ka.s[ki] + Kb.s[kj] - HLN2 * jsum[ki][kj];
                rsum = fmaf(wreg[ki][kj], js, rsum);
            }
            #pragma unroll
            for (int off = 8; off; off >>= 1)
                rsum += __shfl_down_sync(0xffffffffu, rsum, off, 16);
            if (tx == 0) atomicAdd(&g_rowsum[i], rsum);
        }
    }

    // ---- folded finalize: last block to finish reduces everything ----
    __threadfence();
    __syncthreads();
    if (tid == 0) ((int*)sm)[0] = atomicAdd(&g_done, 1);
    __syncthreads();
    int last = (((int*)sm)[0] == NBLK - 1);
    __syncthreads();
    if (!last) return;

    float nega = 0.0f, posi = 0.0f, ood = 0.0f;
    for (int r = tid; r < NROWS; r += NTHR) {
        float rs = __ldcg(&g_rowsum[r]);
        int   rc = __ldcg(&g_rowcnt[r]);
        nega += rs / (float)(rc > 0 ? rc : 1);
    }
    for (int r = tid; r < 2 * NROWS; r += NTHR) {
        posi += g_pos[r];
        ood  += g_oodv[r];
    }
    float* red = sm;
    red[tid]            = nega;
    red[NTHR + tid]     = posi;
    red[2 * NTHR + tid] = ood;
    __syncthreads();
    for (int off = NTHR / 2; off; off >>= 1) {
        if (tid < off) {
            red[tid]            += red[tid + off];
            red[NTHR + tid]     += red[NTHR + tid + off];
            red[2 * NTHR + tid] += red[2 * NTHR + tid + off];
        }
        __syncthreads();
    }
    for (int r = 3 + tid; r < out_size; r += NTHR) out[r] = 0.0f;  // defensive
    if (tid == 0) {
        float ng = red[0];
        float ps = 0.5f * red[NTHR];
        float od = 0.5f * red[2 * NTHR];
        if (out_size > 0) out[0] = ps + ng + 0.5f * od;   // LAM = 0.5
        if (out_size > 1) out[1] = ps;
        if (out_size > 2) out[2] = ng;
    }
}

// ---------------- launch ---------------------------------------------------------
extern "C" void kernel_launch(void* const* d_in, const int* in_sizes, int n_in,
                              void* d_out, int out_size) {
    const float* x1  = (const float*)d_in[0];
    const float* x2  = (const float*)d_in[1];
    const float* xp1 = (const float*)d_in[2];
    const float* xp2 = (const float*)d_in[3];
    const float* l1  = (const float*)d_in[4];
    const float* l2  = (const float*)d_in[5];
    float* out = (float*)d_out;

    row_kernel<<<256, 256>>>(x1, x2, xp1, xp2, l1, l2);

    const int smem_bytes = C * (TI + TJ) * (int)sizeof(float2);   // 49,152 B peak
    cudaFuncSetAttribute(pair_kernel, cudaFuncAttributeMaxDynamicSharedMemorySize,
                         smem_bytes);
    pair_kernel<<<dim3(NROWS / TJ, NROWS / TI), dim3(16, 8), smem_bytes>>>(
        x1, x2, xp1, xp2, l1, l2, out, out_size);
}

// round 17
// speedup vs baseline: 1.1409x; 1.1018x over previous
#include <cuda_runtime.h>
#include <math.h>

#define NROWS 1024
#define C 64
#define MARGIN_F 15.0f
#define EPSJ 1e-8f
#define HLN2 0.34657359027997264f   /* 0.5*ln2 */
#define TI 32                        /* i-tile (rows of x1) */
#define TJ 64                        /* j-tile (rows of x2) */
#define NBLK 512                     /* (1024/TI)*(1024/TJ) */
#define NTHR 128                     /* threads per block (16x8) */

typedef unsigned long long ull;

// ---------------- scratch (static device globals; no allocation) ----------------
__device__ float g_K[2][NROWS];      // 0.5*Sa + 0.5*ln2*sumA  per row
__device__ float g_nn[2][NROWS];     // ||x||^2 per row
__device__ float g_pos[2 * NROWS];   // per-row positive-branch contribution
__device__ float g_oodv[2 * NROWS];  // per-row ood contribution (var*coffi)
__device__ float g_rowsum[NROWS];    // negative-branch per-row pair sums
__device__ int   g_rowcnt[NROWS];    // negative-branch per-row counts
__device__ int   g_done;             // pair-kernel completion counter

__device__ __forceinline__ ull fma2(ull a, ull b, ull c) {
    ull d;
    asm("fma.rn.f32x2 %0, %1, %2, %3;" : "=l"(d) : "l"(a), "l"(b), "l"(c));
    return d;
}

union F4U {
    float4 f;
    ull u[2];
    float s[4];
};

__device__ __forceinline__ float wsum(float v) {
    #pragma unroll
    for (int off = 16; off; off >>= 1) v += __shfl_xor_sync(0xffffffffu, v, off);
    return v;
}
__device__ __forceinline__ float wmin(float v) {
    #pragma unroll
    for (int off = 16; off; off >>= 1)
        v = fminf(v, __shfl_xor_sync(0xffffffffu, v, off));
    return v;
}

// ---------------- kernel 1: warp-per-row precompute + positive + ood ------------
__global__ void row_kernel(const float* __restrict__ x1, const float* __restrict__ x2,
                           const float* __restrict__ xp1, const float* __restrict__ xp2,
                           const float* __restrict__ l1,  const float* __restrict__ l2) {
    int gtid = blockIdx.x * blockDim.x + threadIdx.x;
    int w    = gtid >> 5;            // warp id: 0..2047
    int lane = gtid & 31;
    if (gtid == 0) g_done = 0;
    if (gtid < NROWS) { g_rowsum[gtid] = 0.0f; g_rowcnt[gtid] = 0; }

    int br = w >> 10;
    int i  = w & (NROWS - 1);
    const float* xr = (br ? x2  : x1)  + i * C;
    const float* pr = (br ? xp2 : xp1) + i * C;
    const float* lr = (br ? l2  : l1)  + i * C;

    float xv0 = xr[lane], xv1 = xr[lane + 32];
    float A0  = pr[lane] + EPSJ, A1 = pr[lane + 32] + EPSJ;
    float lv0 = lr[lane], lv1 = lr[lane + 32];

    float nn = wsum(fmaf(xv0, xv0, xv1 * xv1));

    float la0 = __logf(A0),                 la1 = __logf(A1);
    float L00 = __logf(0.5f * (A0 + EPSJ)), L01 = __logf(0.5f * (A1 + EPSJ));
    float L10 = __logf(0.5f * (A0 + 1.0f)), L11 = __logf(0.5f * (A1 + 1.0f));
    float P  = fmaf(A0, la0 - L00, A1 * (la1 - L01));
    float T  = L00 + L01;
    float Sa = fmaf(A0, la0, A1 * la1);
    float sA = A0 + A1;

    float pd0 = sqrtf(fmaxf(nn - 2.0f * xv0 + 1.0f, 1e-12f));
    float pd1 = sqrtf(fmaxf(nn - 2.0f * xv1 + 1.0f, 1e-12f));
    float h0  = -0.5f * A0 * (L00 - L10) - 0.5f * EPSJ * L00 + 0.5f * L10;
    float h1  = -0.5f * A1 * (L01 - L11) - 0.5f * EPSJ * L01 + 0.5f * L11;
    float w0  = pd0 * lv0, w1 = pd1 * lv1;
    float S1  = w0 + w1;
    float S2  = fmaf(w0, h0, w1 * h1);
    float r0  = fmaxf(MARGIN_F - pd0, 0.0f) * (1.0f / MARGIN_F);
    float r1  = fmaxf(MARGIN_F - pd1, 0.0f) * (1.0f / MARGIN_F);
    float var = fmaf(r0, r0, r1 * r1);
    float mn  = fminf(1.0f - r0, 1.0f - r1);

    P = wsum(P); T = wsum(T); Sa = wsum(Sa); sA = wsum(sA);
    S1 = wsum(S1); S2 = wsum(S2); var = wsum(var); mn = wmin(mn);

    if (lane == 0) {
        const float LOGEPS = -18.420680743952367f;   // ln(1e-8)
        float G = 1.0f - 0.5f * P - 0.5f * EPSJ * (float)(C - 1) * LOGEPS
                       + 0.5f * EPSJ * T;
        g_pos [w]   = G * S1 + S2;
        g_oodv[w]   = var * mn;
        g_K [br][i] = 0.5f * Sa + HLN2 * sA;
        g_nn[br][i] = nn;
    }
}

// -------- phase A: grams -> wreg (hinge*(1-dl)) + per-row counts ----------------
__device__ __forceinline__ void do_gram(
    const float* __restrict__ x1, const float* __restrict__ x2,
    const float* __restrict__ l1, const float* __restrict__ l2,
    float* sm, int tx, int ty, int tid, int i0, int j0,
    float (&wreg)[4][4])
{
    float2* sPi = (float2*)sm;            // [C][TI] (l1,x1)  16 KB
    float2* sPj = sPi + C * TI;           // [C][TJ] (l2,x2)  32 KB

    {
        int r = tid & 31, c0 = tid >> 5;          // c0: 0..3
        #pragma unroll
        for (int p = 0; p < 4; p++) {
            int cb = c0 + 4 * p;                  // 0..15
            float4 lv = *(const float4*)&l1[(i0 + r) * C + cb * 4];
            float4 xv = *(const float4*)&x1[(i0 + r) * C + cb * 4];
            sPi[(cb * 4 + 0) * TI + r] = make_float2(lv.x, xv.x);
            sPi[(cb * 4 + 1) * TI + r] = make_float2(lv.y, xv.y);
            sPi[(cb * 4 + 2) * TI + r] = make_float2(lv.z, xv.z);
            sPi[(cb * 4 + 3) * TI + r] = make_float2(lv.w, xv.w);
        }
    }
    {
        int r = tid & 63, c0 = tid >> 6;          // c0: 0..1
        #pragma unroll
        for (int p = 0; p < 8; p++) {
            int cb = c0 + 2 * p;                  // 0..15
            float4 lv = *(const float4*)&l2[(j0 + r) * C + cb * 4];
            float4 xv = *(const float4*)&x2[(j0 + r) * C + cb * 4];
            sPj[(cb * 4 + 0) * TJ + r] = make_float2(lv.x, xv.x);
            sPj[(cb * 4 + 1) * TJ + r] = make_float2(lv.y, xv.y);
            sPj[(cb * 4 + 2) * TJ + r] = make_float2(lv.z, xv.z);
            sPj[(cb * 4 + 3) * TJ + r] = make_float2(lv.w, xv.w);
        }
    }
    __syncthreads();

    ull dlx[4][4];
    #pragma unroll
    for (int a = 0; a < 4; a++)
        #pragma unroll
        for (int b = 0; b < 4; b++) dlx[a][b] = 0ull;

    const float4* pi4 = (const float4*)sPi + ty * 2;
    const float4* pj4 = (const float4*)sPj + tx * 2;

    #pragma unroll 4
    for (int c = 0; c < C; c++) {
        F4U pia, pib, pja, pjb;
        pia.f = pi4[c * (TI / 2)];
        pib.f = pi4[c * (TI / 2) + 1];
        pja.f = pj4[c * (TJ / 2)];
        pjb.f = pj4[c * (TJ / 2) + 1];
        ull pi[4] = {pia.u[0], pia.u[1], pib.u[0], pib.u[1]};
        ull pj[4] = {pja.u[0], pja.u[1], pjb.u[0], pjb.u[1]};
        #pragma unroll
        for (int ki = 0; ki < 4; ki++)
            #pragma unroll
            for (int kj = 0; kj < 4; kj++)
                dlx[ki][kj] = fma2(pi[ki], pj[kj], dlx[ki][kj]);
    }

    F4U nb, na;
    nb.f = *(const float4*)&g_nn[1][j0 + tx * 4];
    na.f = *(const float4*)&g_nn[0][i0 + ty * 4];

    #pragma unroll
    for (int ki = 0; ki < 4; ki++) {
        int rcnt = 0;
        #pragma unroll
        for (int kj = 0; kj < 4; kj++) {
            float2 v = *(float2*)&dlx[ki][kj];           // (dl, dx)
            float d2 = fmaxf(na.s[ki] + nb.s[kj] - 2.0f * v.y, 1e-12f);
            float ed = sqrtf(d2) + 1e-10f;
            float hinge = fmaxf(MARGIN_F - ed, 0.0f);
            float wv = hinge * (1.0f - v.x);             // >0 <=> pair counted
            wreg[ki][kj] = wv;
            rcnt += (wv > 0.0f) ? 1 : 0;
        }
        #pragma unroll
        for (int off = 8; off; off >>= 1)
            rcnt += __shfl_down_sync(0xffffffffu, rcnt, off, 16);
        if (tx == 0) atomicAdd(&g_rowcnt[i0 + ty * 4 + ki], rcnt);
    }
    __syncthreads();   // all smem reads done before caller's next phase overwrites
}

// -------- phase B: js log-sums (pure MUFU) -> jsum ------------------------------
__device__ __forceinline__ void do_js(
    const float* __restrict__ xp1, const float* __restrict__ xp2,
    float* sm, int tx, int ty, int tid, int i0, int j0,
    float (&jsum)[4][4])
{
    float* sA = sm;                       // [C][TI] xp1+eps   8 KB
    float* sB = sm + C * TI;              // [C][TJ] xp2+eps  16 KB

    {
        int r = tid & 31, c0 = tid >> 5;
        #pragma unroll
        for (int p = 0; p < 4; p++) {
            int cb = c0 + 4 * p;
            float4 v = *(const float4*)&xp1[(i0 + r) * C + cb * 4];
            sA[(cb * 4 + 0) * TI + r] = v.x + EPSJ;
            sA[(cb * 4 + 1) * TI + r] = v.y + EPSJ;
            sA[(cb * 4 + 2) * TI + r] = v.z + EPSJ;
            sA[(cb * 4 + 3) * TI + r] = v.w + EPSJ;
        }
    }
    {
        int r = tid & 63, c0 = tid >> 6;
        #pragma unroll
        for (int p = 0; p < 8; p++) {
            int cb = c0 + 2 * p;
            float4 v = *(const float4*)&xp2[(j0 + r) * C + cb * 4];
            sB[(cb * 4 + 0) * TJ + r] = v.x + EPSJ;
            sB[(cb * 4 + 1) * TJ + r] = v.y + EPSJ;
            sB[(cb * 4 + 2) * TJ + r] = v.z + EPSJ;
            sB[(cb * 4 + 3) * TJ + r] = v.w + EPSJ;
        }
    }
    __syncthreads();

    #pragma unroll
    for (int a = 0; a < 4; a++)
        #pragma unroll
        for (int b = 0; b < 4; b++) jsum[a][b] = 0.0f;

    const float4* a4 = (const float4*)sA + ty;      // stride TI/4=8 per c
    const float4* b4 = (const float4*)sB + tx;      // stride TJ/4=16 per c

    #pragma unroll 4
    for (int c = 0; c < C; c++) {
        F4U av, bv;
        av.f = a4[c * (TI / 4)];
        bv.f = b4[c * (TJ / 4)];
        #pragma unroll
        for (int ki = 0; ki < 4; ki++)
            #pragma unroll
            for (int kj = 0; kj < 4; kj++) {
                float s = av.s[ki] + bv.s[kj];
                jsum[ki][kj] = fmaf(s, __log2f(s), jsum[ki][kj]);   // MUFU.LG2
            }
    }
    __syncthreads();   // all smem reads done before caller's next phase overwrites
}

// ---------------- kernel 2: pairwise negative branch, PHASE-STAGGERED -----------
// Round-7 fused skeleton (all-time best). New: half the blocks per SM run the
// MUFU-heavy js phase FIRST and the fma-heavy gram phase SECOND. With the
// classic bid->SM placement (LUT[bid % 148]), an SM's 4 resident blocks have
// linear ids {id, id+148, id+296, id+444} -> slots 0..3 -> 2 A-first + 2
// B-first per SM. Both pipes (fma ~30k cyc total, MUFU ~28k) now run
// CONCURRENTLY instead of chip-wide phase lockstep (wall = sum -> wall = max).
__global__ void __launch_bounds__(NTHR, 4)
pair_kernel(const float* __restrict__ x1, const float* __restrict__ x2,
            const float* __restrict__ xp1, const float* __restrict__ xp2,
            const float* __restrict__ l1,  const float* __restrict__ l2,
            float* __restrict__ out, int out_size) {
    extern __shared__ float sm[];
    const int tx = threadIdx.x, ty = threadIdx.y;
    const int tid = ty * 16 + tx;
    const int i0 = blockIdx.y * TI, j0 = blockIdx.x * TJ;
    const int linear = blockIdx.y * gridDim.x + blockIdx.x;
    const int bfirst = (linear / 148) & 1;     // wave-slot parity on each SM

    float wreg[4][4];
    float jsum[4][4];

    if (bfirst) {
        do_js  (xp1, xp2, sm, tx, ty, tid, i0, j0, jsum);
        do_gram(x1, x2, l1, l2, sm, tx, ty, tid, i0, j0, wreg);
    } else {
        do_gram(x1, x2, l1, l2, sm, tx, ty, tid, i0, j0, wreg);
        do_js  (xp1, xp2, sm, tx, ty, tid, i0, j0, jsum);
    }

    // ---- combine ----
    {
        F4U Kb, Ka;
        Kb.f = *(const float4*)&g_K[1][j0 + tx * 4];
        Ka.f = *(const float4*)&g_K[0][i0 + ty * 4];

        #pragma unroll
        for (int ki = 0; ki < 4; ki++) {
            int i = i0 + ty * 4 + ki;
            float rsum = 0.0f;
            #pragma unroll
            for (int kj = 0; kj < 4; kj++) {
                float js = Ka.s[ki] + Kb.s[kj] - HLN2 * jsum[ki][kj];
                rsum = fmaf(wreg[ki][kj], js, rsum);
            }
            #pragma unroll
            for (int off = 8; off; off >>= 1)
                rsum += __shfl_down_sync(0xffffffffu, rsum, off, 16);
            if (tx == 0) atomicAdd(&g_rowsum[i], rsum);
        }
    }

    // ---- folded finalize: last block to finish reduces everything ----
    __threadfence();
    __syncthreads();
    if (tid == 0) ((int*)sm)[0] = atomicAdd(&g_done, 1);
    __syncthreads();
    int last = (((int*)sm)[0] == NBLK - 1);
    __syncthreads();
    if (!last) return;

    float nega = 0.0f, posi = 0.0f, ood = 0.0f;
    for (int r = tid; r < NROWS; r += NTHR) {
        float rs = __ldcg(&g_rowsum[r]);
        int   rc = __ldcg(&g_rowcnt[r]);
        nega += rs / (float)(rc > 0 ? rc : 1);
    }
    for (int r = tid; r < 2 * NROWS; r += NTHR) {
        posi += g_pos[r];
        ood  += g_oodv[r];
    }
    float* red = sm;
    red[tid]            = nega;
    red[NTHR + tid]     = posi;
    red[2 * NTHR + tid] = ood;
    __syncthreads();
    for (int off = NTHR / 2; off; off >>= 1) {
        if (tid < off) {
            red[tid]            += red[tid + off];
            red[NTHR + tid]     += red[NTHR + tid + off];
            red[2 * NTHR + tid] += red[2 * NTHR + tid + off];
        }
        __syncthreads();
    }
    for (int r = 3 + tid; r < out_size; r += NTHR) out[r] = 0.0f;  // defensive
    if (tid == 0) {
        float ng = red[0];
        float ps = 0.5f * red[NTHR];
        float od = 0.5f * red[2 * NTHR];
        if (out_size > 0) out[0] = ps + ng + 0.5f * od;   // LAM = 0.5
        if (out_size > 1) out[1] = ps;
        if (out_size > 2) out[2] = ng;
    }
}

// ---------------- launch ---------------------------------------------------------
extern "C" void kernel_launch(void* const* d_in, const int* in_sizes, int n_in,
                              void* d_out, int out_size) {
    const float* x1  = (const float*)d_in[0];
    const float* x2  = (const float*)d_in[1];
    const float* xp1 = (const float*)d_in[2];
    const float* xp2 = (const float*)d_in[3];
    const float* l1  = (const float*)d_in[4];
    const float* l2  = (const float*)d_in[5];
    float* out = (float*)d_out;

    row_kernel<<<256, 256>>>(x1, x2, xp1, xp2, l1, l2);

    const int smem_bytes = C * (TI + TJ) * (int)sizeof(float2);   // 49,152 B peak
    cudaFuncSetAttribute(pair_kernel, cudaFuncAttributeMaxDynamicSharedMemorySize,
                         smem_bytes);
    pair_kernel<<<dim3(NROWS / TJ, NROWS / TI), dim3(16, 8), smem_bytes>>>(
        x1, x2, xp1, xp2, l1, l2, out, out_size);
}